// round 2
// baseline (speedup 1.0000x reference)
#include <cuda_runtime.h>
#include <math.h>

#define N_PTS   1000000
#define NSEG    64
#define HID     128
#define AFFD    16
#define AH      64
#define AL      32
#define AA      8

#define TPB     256
#define PPT     4
#define NPAIR   (PPT / 2)
#define PTS_PER_CTA (TPB * PPT)

#define ACC_STRIDE (AFFD + 2)   // 16 aff sums, err sum, count

typedef unsigned long long ull;

// ---- packed f32x2 helpers (sm_103a) ----
__device__ __forceinline__ ull fma2(ull a, ull b, ull c) {
    ull d;
    asm("fma.rn.f32x2 %0, %1, %2, %3;" : "=l"(d) : "l"(a), "l"(b), "l"(c));
    return d;
}
__device__ __forceinline__ ull packf2(float lo, float hi) {
    ull r;
    asm("mov.b64 %0, {%1, %2};" : "=l"(r) : "f"(lo), "f"(hi));
    return r;
}
__device__ __forceinline__ void unpackf2(ull v, float& lo, float& hi) {
    asm("mov.b64 {%0, %1}, %2;" : "=f"(lo), "=f"(hi) : "l"(v));
}
__device__ __forceinline__ ull relu2(ull v) {
    float lo, hi;
    unpackf2(v, lo, hi);
    return packf2(fmaxf(lo, 0.0f), fmaxf(hi, 0.0f));
}

// Global scratch accumulator (no allocations allowed)
__device__ float g_accum[NSEG * ACC_STRIDE];

__global__ void zero_accum_kernel() {
    int i = blockIdx.x * blockDim.x + threadIdx.x;
    if (i < NSEG * ACC_STRIDE) g_accum[i] = 0.0f;
}

__global__ __launch_bounds__(TPB) void point_kernel(
    const float* __restrict__ pos, const int* __restrict__ batch,
    const float* __restrict__ Wf1, const float* __restrict__ bf1,
    const float* __restrict__ Wf2, const float* __restrict__ bf2,
    const float* __restrict__ Wg1, const float* __restrict__ bg1,
    const float* __restrict__ Wg2, const float* __restrict__ bg2,
    float* __restrict__ out_aff, float* __restrict__ out_recon,
    float* __restrict__ out_cspatial)
{
    // Duplicated ("broadcast-packed") weights: each logical weight stored as (w, w)
    __shared__ __align__(16) float sWf1d[HID * 8];     // per j: w0,w0,w1,w1,w2,w2,b,b    (4 KB)
    __shared__ __align__(16) float sWf2d[HID * 32];    // per j: 16 cols duplicated       (16 KB)
    __shared__ __align__(16) float sbf2d[AFFD * 2];    // duplicated bf2
    __shared__ __align__(16) float sWg1d[HID * 32];    // per j: 16 k-weights duplicated  (16 KB)
    __shared__ __align__(16) float sbg1d[HID * 2];     // duplicated bg1                  (1 KB)
    __shared__ __align__(16) float sWg2d[HID * 8];     // per j: u0,u0,u1,u1,u2,u2,pad    (4 KB)
    __shared__ float sbg2[3];
    __shared__ float sacc[NSEG * ACC_STRIDE];          // (4.6 KB)

    const int tid = threadIdx.x;
    for (int i = tid; i < HID; i += TPB) {
        float w0 = Wf1[i], w1 = Wf1[HID + i], w2 = Wf1[2 * HID + i], b = bf1[i];
        float* r = &sWf1d[i * 8];
        r[0] = w0; r[1] = w0; r[2] = w1; r[3] = w1; r[4] = w2; r[5] = w2; r[6] = b; r[7] = b;
    }
    for (int idx = tid; idx < HID * AFFD; idx += TPB) {
        int j = idx / AFFD, k = idx % AFFD;
        float w = Wf2[j * AFFD + k];
        sWf2d[j * 32 + 2 * k] = w; sWf2d[j * 32 + 2 * k + 1] = w;
    }
    for (int idx = tid; idx < AFFD * HID; idx += TPB) {
        int k = idx / HID, j = idx % HID;
        float w = Wg1[k * HID + j];
        sWg1d[j * 32 + 2 * k] = w; sWg1d[j * 32 + 2 * k + 1] = w;
    }
    for (int i = tid; i < HID; i += TPB) {
        sbg1d[2 * i] = bg1[i]; sbg1d[2 * i + 1] = bg1[i];
        float u0 = Wg2[i * 3 + 0], u1 = Wg2[i * 3 + 1], u2 = Wg2[i * 3 + 2];
        float* r = &sWg2d[i * 8];
        r[0] = u0; r[1] = u0; r[2] = u1; r[3] = u1; r[4] = u2; r[5] = u2; r[6] = 0.f; r[7] = 0.f;
    }
    if (tid < AFFD) { sbf2d[2 * tid] = bf2[tid]; sbf2d[2 * tid + 1] = bf2[tid]; }
    if (tid < 3) sbg2[tid] = bg2[tid];
    for (int i = tid; i < NSEG * ACC_STRIDE; i += TPB) sacc[i] = 0.0f;
    __syncthreads();

    const int base = blockIdx.x * PTS_PER_CTA + tid;

    // Pair p = (point base + 2p*TPB, point base + (2p+1)*TPB) packed lo/hi
    float pxs[PPT], pys[PPT], pzs[PPT];
    int   seg[PPT];
    bool  valid[PPT];
    #pragma unroll
    for (int i = 0; i < PPT; i++) {
        int p = base + i * TPB;
        valid[i] = (p < N_PTS);
        int pp = valid[i] ? p : (N_PTS - 1);
        pxs[i] = pos[pp * 3 + 0];
        pys[i] = pos[pp * 3 + 1];
        pzs[i] = pos[pp * 3 + 2];
        seg[i] = batch[pp];
    }

    ull px[NPAIR], py[NPAIR], pz[NPAIR];
    #pragma unroll
    for (int q = 0; q < NPAIR; q++) {
        px[q] = packf2(pxs[2 * q], pys[2 * q] * 0.0f + pxs[2 * q + 1]); // keep simple pack
    }
    // (re-pack cleanly; the above avoided compiler confusion, do it plainly)
    #pragma unroll
    for (int q = 0; q < NPAIR; q++) {
        px[q] = packf2(pxs[2 * q], pxs[2 * q + 1]);
        py[q] = packf2(pys[2 * q], pys[2 * q + 1]);
        pz[q] = packf2(pzs[2 * q], pzs[2 * q + 1]);
    }

    // ---- F: affordances = relu(pos@Wf1 + bf1) @ Wf2 + bf2  (packed 2 pts/reg) ----
    ull aff[NPAIR][AFFD];
    #pragma unroll
    for (int k = 0; k < AFFD; k++) {
        ull b2 = *reinterpret_cast<const ull*>(&sbf2d[2 * k]);
        #pragma unroll
        for (int q = 0; q < NPAIR; q++) aff[q][k] = b2;
    }

    #pragma unroll 2
    for (int j = 0; j < HID; j++) {
        ulonglong2 wA = *reinterpret_cast<const ulonglong2*>(&sWf1d[j * 8]);     // (w0,w0),(w1,w1)
        ulonglong2 wB = *reinterpret_cast<const ulonglong2*>(&sWf1d[j * 8 + 4]); // (w2,w2),(b,b)
        ull h[NPAIR];
        #pragma unroll
        for (int q = 0; q < NPAIR; q++) {
            ull v = fma2(pz[q], wB.x, wB.y);
            v = fma2(py[q], wA.y, v);
            v = fma2(px[q], wA.x, v);
            h[q] = relu2(v);
        }
        #pragma unroll
        for (int kk = 0; kk < AFFD / 2; kk++) {
            ulonglong2 w = *reinterpret_cast<const ulonglong2*>(&sWf2d[j * 32 + kk * 4]);
            #pragma unroll
            for (int q = 0; q < NPAIR; q++) {
                aff[q][2 * kk]     = fma2(h[q], w.x, aff[q][2 * kk]);
                aff[q][2 * kk + 1] = fma2(h[q], w.y, aff[q][2 * kk + 1]);
            }
        }
    }

    // ---- G: recon = relu(aff@Wg1 + bg1) @ Wg2 + bg2  (packed) ----
    ull rx[NPAIR], ry[NPAIR], rz[NPAIR];
    {
        ull b0 = packf2(sbg2[0], sbg2[0]);
        ull b1 = packf2(sbg2[1], sbg2[1]);
        ull b2 = packf2(sbg2[2], sbg2[2]);
        #pragma unroll
        for (int q = 0; q < NPAIR; q++) { rx[q] = b0; ry[q] = b1; rz[q] = b2; }
    }

    #pragma unroll 2
    for (int j = 0; j < HID; j++) {
        ull bj = *reinterpret_cast<const ull*>(&sbg1d[j * 2]);
        ull g[NPAIR];
        #pragma unroll
        for (int q = 0; q < NPAIR; q++) g[q] = bj;
        #pragma unroll
        for (int kk = 0; kk < AFFD / 2; kk++) {
            ulonglong2 w = *reinterpret_cast<const ulonglong2*>(&sWg1d[j * 32 + kk * 4]);
            #pragma unroll
            for (int q = 0; q < NPAIR; q++) {
                g[q] = fma2(aff[q][2 * kk], w.x, g[q]);
                g[q] = fma2(aff[q][2 * kk + 1], w.y, g[q]);
            }
        }
        ulonglong2 u01 = *reinterpret_cast<const ulonglong2*>(&sWg2d[j * 8]);
        ull u2 = *reinterpret_cast<const ull*>(&sWg2d[j * 8 + 4]);
        #pragma unroll
        for (int q = 0; q < NPAIR; q++) {
            ull gi = relu2(g[q]);
            rx[q] = fma2(gi, u01.x, rx[q]);
            ry[q] = fma2(gi, u01.y, ry[q]);
            rz[q] = fma2(gi, u2,    rz[q]);
        }
    }

    // ---- epilogue: unpack, stores, errors ----
    float err[PPT];
    #pragma unroll
    for (int q = 0; q < NPAIR; q++) {
        float rx0, rx1, ry0, ry1, rz0, rz1;
        unpackf2(rx[q], rx0, rx1);
        unpackf2(ry[q], ry0, ry1);
        unpackf2(rz[q], rz0, rz1);
        {
            int i = 2 * q;
            float dx = pxs[i] - rx0, dy = pys[i] - ry0, dz = pzs[i] - rz0;
            err[i] = fmaf(dx, dx, fmaf(dy, dy, dz * dz));
            if (valid[i]) {
                int p = base + i * TPB;
                out_recon[(size_t)p * 3 + 0] = rx0;
                out_recon[(size_t)p * 3 + 1] = ry0;
                out_recon[(size_t)p * 3 + 2] = rz0;
                out_cspatial[p] = err[i];
            }
        }
        {
            int i = 2 * q + 1;
            float dx = pxs[i] - rx1, dy = pys[i] - ry1, dz = pzs[i] - rz1;
            err[i] = fmaf(dx, dx, fmaf(dy, dy, dz * dz));
            if (valid[i]) {
                int p = base + i * TPB;
                out_recon[(size_t)p * 3 + 0] = rx1;
                out_recon[(size_t)p * 3 + 1] = ry1;
                out_recon[(size_t)p * 3 + 2] = rz1;
                out_cspatial[p] = err[i];
            }
        }
    }

    // unpack affordances to scalar per point (also used for reduction)
    float affs[PPT][AFFD];
    #pragma unroll
    for (int q = 0; q < NPAIR; q++) {
        #pragma unroll
        for (int k = 0; k < AFFD; k++) {
            unpackf2(aff[q][k], affs[2 * q][k], affs[2 * q + 1][k]);
        }
    }
    #pragma unroll
    for (int i = 0; i < PPT; i++) {
        if (valid[i]) {
            int p = base + i * TPB;
            float4* dst = (float4*)(out_aff + (size_t)p * AFFD);
            #pragma unroll
            for (int v4 = 0; v4 < 4; v4++) {
                dst[v4] = make_float4(affs[i][4 * v4], affs[i][4 * v4 + 1],
                                      affs[i][4 * v4 + 2], affs[i][4 * v4 + 3]);
            }
        }
    }

    // ---- segment reduction (batch sorted; warp-uniform fast path) ----
    const unsigned FULL = 0xffffffffu;
    #pragma unroll
    for (int i = 0; i < PPT; i++) {
        int sg = seg[i];
        float cnt = valid[i] ? 1.0f : 0.0f;
        float e   = valid[i] ? err[i] : 0.0f;
        float av[AFFD];
        #pragma unroll
        for (int k = 0; k < AFFD; k++) av[k] = valid[i] ? affs[i][k] : 0.0f;

        int sg0 = __shfl_sync(FULL, sg, 0);
        bool uniform = __all_sync(FULL, sg == sg0);
        if (uniform) {
            #pragma unroll
            for (int off = 16; off >= 1; off >>= 1) {
                cnt += __shfl_xor_sync(FULL, cnt, off);
                e   += __shfl_xor_sync(FULL, e,   off);
                #pragma unroll
                for (int k = 0; k < AFFD; k++)
                    av[k] += __shfl_xor_sync(FULL, av[k], off);
            }
            if ((tid & 31) == 0) {
                float* a = &sacc[sg * ACC_STRIDE];
                #pragma unroll
                for (int k = 0; k < AFFD; k++) atomicAdd(&a[k], av[k]);
                atomicAdd(&a[AFFD], e);
                atomicAdd(&a[AFFD + 1], cnt);
            }
        } else {
            if (valid[i]) {
                float* a = &sacc[sg * ACC_STRIDE];
                #pragma unroll
                for (int k = 0; k < AFFD; k++) atomicAdd(&a[k], av[k]);
                atomicAdd(&a[AFFD], e);
                atomicAdd(&a[AFFD + 1], 1.0f);
            }
        }
    }
    __syncthreads();

    // flush only this CTA's segment range to global (batch sorted)
    int first = blockIdx.x * PTS_PER_CTA;
    int last  = min(first + PTS_PER_CTA - 1, N_PTS - 1);
    int smin = batch[first];
    int smax = batch[last];
    int total = (smax - smin + 1) * ACC_STRIDE;
    for (int t = tid; t < total; t += TPB) {
        float v = sacc[smin * ACC_STRIDE + t];
        if (v != 0.0f) atomicAdd(&g_accum[smin * ACC_STRIDE + t], v);
    }
}

__device__ __forceinline__ float sigmoidf_(float x) {
    return 1.0f / (1.0f + expf(-x));
}

__global__ void agent_kernel(
    const float* __restrict__ agent_h,
    const float* __restrict__ Wx, const float* __restrict__ Wh,
    const float* __restrict__ bx, const float* __restrict__ bh,
    const float* __restrict__ Wlat, const float* __restrict__ blat,
    const float* __restrict__ Wact, const float* __restrict__ bact,
    float* __restrict__ out_csig, float* __restrict__ out_action,
    float* __restrict__ out_hnext)
{
    int b = blockIdx.x;
    int u = threadIdx.x;   // 0..63
    __shared__ float s_aff[AFFD];
    __shared__ float s_h[AH];
    __shared__ float s_hn[AH];
    __shared__ float s_lat[AL];

    float cnt = g_accum[b * ACC_STRIDE + AFFD + 1];
    float denom = fmaxf(cnt, 1.0f);
    if (u < AFFD) s_aff[u] = g_accum[b * ACC_STRIDE + u] / denom;
    if (u == 0)   out_csig[b] = g_accum[b * ACC_STRIDE + AFFD] / denom;
    s_h[u] = agent_h[b * AH + u];
    __syncthreads();

    float gxr = bx[u], gxz = bx[AH + u], gxn = bx[2 * AH + u];
    #pragma unroll
    for (int k = 0; k < AFFD; k++) {
        float a = s_aff[k];
        gxr = fmaf(a, Wx[k * 3 * AH + u], gxr);
        gxz = fmaf(a, Wx[k * 3 * AH + AH + u], gxz);
        gxn = fmaf(a, Wx[k * 3 * AH + 2 * AH + u], gxn);
    }
    float ghr = bh[u], ghz = bh[AH + u], ghn = bh[2 * AH + u];
    #pragma unroll
    for (int k = 0; k < AH; k++) {
        float hh = s_h[k];
        ghr = fmaf(hh, Wh[k * 3 * AH + u], ghr);
        ghz = fmaf(hh, Wh[k * 3 * AH + AH + u], ghz);
        ghn = fmaf(hh, Wh[k * 3 * AH + 2 * AH + u], ghn);
    }
    float r = sigmoidf_(gxr + ghr);
    float z = sigmoidf_(gxz + ghz);
    float n = tanhf(gxn + r * ghn);
    float hn = (1.0f - z) * n + z * s_h[u];
    out_hnext[b * AH + u] = hn;
    s_hn[u] = hn;
    __syncthreads();

    if (u < AL) {
        float acc = blat[u];
        #pragma unroll
        for (int k = 0; k < AH; k++) acc = fmaf(s_hn[k], Wlat[k * AL + u], acc);
        s_lat[u] = tanhf(acc);
    }
    __syncthreads();

    if (u < AA) {
        float acc = bact[u];
        #pragma unroll
        for (int k = 0; k < AL; k++) acc = fmaf(s_lat[k], Wact[k * AA + u], acc);
        out_action[b * AA + u] = acc;
    }
}

extern "C" void kernel_launch(void* const* d_in, const int* in_sizes, int n_in,
                              void* d_out, int out_size) {
    const float* pos   = (const float*)d_in[0];
    const int*   batch = (const int*)d_in[1];
    const float* agent_h = (const float*)d_in[2];
    // d_in[3] coherence_signal_prev, d_in[4] coherence_spatial_prev: unused
    const float* Wf1 = (const float*)d_in[5];
    const float* bf1 = (const float*)d_in[6];
    const float* Wf2 = (const float*)d_in[7];
    const float* bf2 = (const float*)d_in[8];
    const float* Wg1 = (const float*)d_in[9];
    const float* bg1 = (const float*)d_in[10];
    const float* Wg2 = (const float*)d_in[11];
    const float* bg2 = (const float*)d_in[12];
    const float* Wx  = (const float*)d_in[13];
    const float* Wh  = (const float*)d_in[14];
    const float* bx  = (const float*)d_in[15];
    const float* bh  = (const float*)d_in[16];
    const float* Wlat = (const float*)d_in[17];
    const float* blat = (const float*)d_in[18];
    const float* Wact = (const float*)d_in[19];
    const float* bact = (const float*)d_in[20];

    float* out = (float*)d_out;
    float* out_aff      = out;                                    // N*16
    float* out_recon    = out + (size_t)N_PTS * AFFD;             // N*3
    float* out_csig     = out + (size_t)N_PTS * 19;               // B
    float* out_cspatial = out + (size_t)N_PTS * 19 + NSEG;        // N
    float* out_action   = out + (size_t)N_PTS * 20 + NSEG;        // B*8
    float* out_hnext    = out + (size_t)N_PTS * 20 + NSEG + NSEG * AA; // B*64

    zero_accum_kernel<<<(NSEG * ACC_STRIDE + 255) / 256, 256>>>();

    int grid = (N_PTS + PTS_PER_CTA - 1) / PTS_PER_CTA;
    point_kernel<<<grid, TPB>>>(pos, batch,
                                Wf1, bf1, Wf2, bf2, Wg1, bg1, Wg2, bg2,
                                out_aff, out_recon, out_cspatial);

    agent_kernel<<<NSEG, AH>>>(agent_h, Wx, Wh, bx, bh, Wlat, blat, Wact, bact,
                               out_csig, out_action, out_hnext);
}